// round 1
// baseline (speedup 1.0000x reference)
#include <cuda_runtime.h>
#include <cuda_bf16.h>

#define BSZ 4
#define NSQ 16384
#define SSAMP 8
#define CPL 64
#define RESOL 128
#define HWSZ (RESOL * RESOL)
#define IND 192
#define NPTS (BSZ * NSQ)   // 65536

// ---------------- scratch (static device globals; no allocation) ----------------
__device__ float g_planes[(size_t)BSZ * 3 * HWSZ * CPL];  // channel-last [b][p][y][x][c]
__device__ float g_feat[(size_t)NPTS * IND];
__device__ float g_off[(size_t)NPTS * 24];
__device__ float g_wt[(size_t)NPTS * 8];
__device__ float g_auxw[(size_t)NPTS * IND];
__device__ float g_wtsum[NPTS];
__device__ float g_tmp[(size_t)NPTS * IND];

// ---------------- 1) transpose planes to channel-last ----------------
// grid (HW/32, B, 3), block (32, 8)
__global__ void transpose_planes(const float* __restrict__ pxz,
                                 const float* __restrict__ pxy,
                                 const float* __restrict__ pyz) {
    int p = blockIdx.z;
    int b = blockIdx.y;
    int yx0 = blockIdx.x * 32;
    const float* src = (p == 0 ? pxz : (p == 1 ? pxy : pyz)) + (size_t)b * CPL * HWSZ;
    float* dst = g_planes + (size_t)(b * 3 + p) * HWSZ * CPL;

    __shared__ float tile[CPL][33];
    int tx = threadIdx.x, ty = threadIdx.y;
#pragma unroll
    for (int cb = 0; cb < CPL; cb += 8) {
        int c = cb + ty;
        tile[c][tx] = src[(size_t)c * HWSZ + yx0 + tx];
    }
    __syncthreads();
    int t = ty * 32 + tx;
#pragma unroll
    for (int i = 0; i < 8; i++) {
        int e = i * 256 + t;
        int c = e & 63;
        int yxl = e >> 6;
        dst[(size_t)(yx0 + yxl) * CPL + c] = tile[c][yxl];
    }
}

// ---------------- bilinear sample helper (channel-last planes) ----------------
__device__ __forceinline__ float sample_one(int b, int p, int ch, float u, float v) {
    float x = fminf(fmaxf(u, 0.0f), 1.0f) * (float)(RESOL - 1);
    float y = fminf(fmaxf(v, 0.0f), 1.0f) * (float)(RESOL - 1);
    float xf = floorf(x), yf = floorf(y);
    int ix0 = (int)xf, iy0 = (int)yf;
    int ix1 = min(ix0 + 1, RESOL - 1);
    int iy1 = min(iy0 + 1, RESOL - 1);
    float wx = x - xf, wy = y - yf;
    const float* base = g_planes + (size_t)(b * 3 + p) * HWSZ * CPL + ch;
    float f00 = base[(size_t)(iy0 * RESOL + ix0) * CPL];
    float f01 = base[(size_t)(iy0 * RESOL + ix1) * CPL];
    float f10 = base[(size_t)(iy1 * RESOL + ix0) * CPL];
    float f11 = base[(size_t)(iy1 * RESOL + ix1) * CPL];
    return f00 * (1.0f - wx) * (1.0f - wy) + f01 * wx * (1.0f - wy)
         + f10 * (1.0f - wx) * wy + f11 * wx * wy;
}

// ---------------- 2) sample features at query points ----------------
// grid NPTS, block IND(192)
__global__ void sample_query(const float* __restrict__ qp) {
    int pt = blockIdx.x;
    int c = threadIdx.x;
    int b = pt >> 14;  // pt / NSQ
    int p = c >> 6, ch = c & 63;
    float px = qp[pt * 3 + 0], py = qp[pt * 3 + 1], pz = qp[pt * 3 + 2];
    float u = (p == 2) ? py : px;
    float v = (p == 1) ? py : pz;
    g_feat[(size_t)pt * IND + c] = sample_one(b, p, ch, u, v);
}

// ---------------- 5) sample offset points, weighted-accumulate ----------------
// grid NPTS, block IND(192)
__global__ void sample_aux(const float* __restrict__ qp) {
    int pt = blockIdx.x;
    int c = threadIdx.x;
    int b = pt >> 14;
    int p = c >> 6, ch = c & 63;
    float px = qp[pt * 3 + 0], py = qp[pt * 3 + 1], pz = qp[pt * 3 + 2];
    const float* offr = g_off + (size_t)pt * 24;
    const float* wtr = g_wt + (size_t)pt * 8;
    float acc = 0.0f, wts = 0.0f;
#pragma unroll
    for (int s = 0; s < SSAMP; s++) {
        float qx = px + offr[s * 3 + 0];
        float qy = py + offr[s * 3 + 1];
        float qz = pz + offr[s * 3 + 2];
        float w = wtr[s];
        float u = (p == 2) ? qy : qx;
        float v = (p == 1) ? qy : qz;
        acc += w * sample_one(b, p, ch, u, v);
        wts += w;
    }
    g_auxw[(size_t)pt * IND + c] = acc;
    if (c == 0) g_wtsum[pt] = wts;
}

// ---------------- tiled fp32 GEMM: C[m,n] = sum_k A[m,k]*W[n,k] + epilogue --------
// BM=64 BN=64 BK=16, 256 threads, 4x4 microtile.
// epilogue: C = acc + bias[n]*(rowscale?rowscale[m]:1) + (addmat?addmat[m,n]:0)
__global__ __launch_bounds__(256) void gemm_bias(
    const float* __restrict__ A, const float* __restrict__ W,
    float* __restrict__ C, int M, int N, int K,
    const float* __restrict__ bias,
    const float* __restrict__ rowscale,
    const float* __restrict__ addmat) {
    const int BM = 64, BN = 64, BK = 16;
    __shared__ float As[BK][BM];
    __shared__ float Ws[BK][BN];
    int m0 = blockIdx.x * BM;
    int n0 = blockIdx.y * BN;
    int tid = threadIdx.x;
    int tx = tid & 15, ty = tid >> 4;

    float acc[4][4] = {};
    int lm = tid >> 2;          // 0..63
    int lk4 = (tid & 3) * 4;    // 0,4,8,12

    for (int k0 = 0; k0 < K; k0 += BK) {
        float4 av = *reinterpret_cast<const float4*>(&A[(size_t)(m0 + lm) * K + k0 + lk4]);
        float4 wv = make_float4(0.f, 0.f, 0.f, 0.f);
        int wn = n0 + lm;
        if (wn < N)
            wv = *reinterpret_cast<const float4*>(&W[(size_t)wn * K + k0 + lk4]);
        __syncthreads();
        As[lk4 + 0][lm] = av.x; As[lk4 + 1][lm] = av.y;
        As[lk4 + 2][lm] = av.z; As[lk4 + 3][lm] = av.w;
        Ws[lk4 + 0][lm] = wv.x; Ws[lk4 + 1][lm] = wv.y;
        Ws[lk4 + 2][lm] = wv.z; Ws[lk4 + 3][lm] = wv.w;
        __syncthreads();
#pragma unroll
        for (int k = 0; k < BK; k++) {
            float4 a4 = *reinterpret_cast<const float4*>(&As[k][ty * 4]);
            float4 w4 = *reinterpret_cast<const float4*>(&Ws[k][tx * 4]);
            float a[4] = {a4.x, a4.y, a4.z, a4.w};
            float w[4] = {w4.x, w4.y, w4.z, w4.w};
#pragma unroll
            for (int i = 0; i < 4; i++)
#pragma unroll
                for (int j = 0; j < 4; j++)
                    acc[i][j] += a[i] * w[j];
        }
    }

#pragma unroll
    for (int i = 0; i < 4; i++) {
        int m = m0 + ty * 4 + i;
#pragma unroll
        for (int j = 0; j < 4; j++) {
            int n = n0 + tx * 4 + j;
            if (n < N) {
                float v = acc[i][j] + bias[n] * (rowscale ? rowscale[m] : 1.0f);
                if (addmat) v += addmat[(size_t)m * N + n];
                C[(size_t)m * N + n] = v;
            }
        }
    }
}

// ---------------- launch ----------------
extern "C" void kernel_launch(void* const* d_in, const int* in_sizes, int n_in,
                              void* d_out, int out_size) {
    const float* qp    = (const float*)d_in[0];
    const float* fxz   = (const float*)d_in[1];
    const float* fxy   = (const float*)d_in[2];
    const float* fyz   = (const float*)d_in[3];
    const float* W_v   = (const float*)d_in[4];
    const float* b_v   = (const float*)d_in[5];
    const float* W_out = (const float*)d_in[6];
    const float* b_out = (const float*)d_in[7];
    const float* W_off = (const float*)d_in[8];
    const float* b_off = (const float*)d_in[9];
    const float* W_wt  = (const float*)d_in[10];
    const float* b_wt  = (const float*)d_in[11];
    float* out = (float*)d_out;

    float *p_feat, *p_off, *p_wt, *p_auxw, *p_wtsum, *p_tmp;
    cudaGetSymbolAddress((void**)&p_feat, g_feat);
    cudaGetSymbolAddress((void**)&p_off, g_off);
    cudaGetSymbolAddress((void**)&p_wt, g_wt);
    cudaGetSymbolAddress((void**)&p_auxw, g_auxw);
    cudaGetSymbolAddress((void**)&p_wtsum, g_wtsum);
    cudaGetSymbolAddress((void**)&p_tmp, g_tmp);

    // 1) planes -> channel-last
    transpose_planes<<<dim3(HWSZ / 32, BSZ, 3), dim3(32, 8)>>>(fxz, fxy, fyz);
    // 2) feature at query points
    sample_query<<<NPTS, IND>>>(qp);
    // 3) off = feat @ W_off^T + b_off  (N=24)
    gemm_bias<<<dim3(NPTS / 64, 1), 256>>>(p_feat, W_off, p_off, NPTS, 24, IND,
                                           b_off, nullptr, nullptr);
    // 4) wt = feat @ W_wt^T + b_wt  (N=8)
    gemm_bias<<<dim3(NPTS / 64, 1), 256>>>(p_feat, W_wt, p_wt, NPTS, 8, IND,
                                           b_wt, nullptr, nullptr);
    // 5) auxw = sum_s wt_s * sample(pts_s);  wtsum = sum_s wt_s
    sample_aux<<<NPTS, IND>>>(qp);
    // 6) tmp = auxw @ W_v^T + b_v * wtsum   (linearity: == sum_s wt_s * v_s)
    gemm_bias<<<dim3(NPTS / 64, 3), 256>>>(p_auxw, W_v, p_tmp, NPTS, IND, IND,
                                           b_v, p_wtsum, nullptr);
    // 7) out = tmp @ W_out^T + b_out + feat
    gemm_bias<<<dim3(NPTS / 64, 3), 256>>>(p_tmp, W_out, out, NPTS, IND, IND,
                                           b_out, nullptr, p_feat);
}

// round 3
// speedup vs baseline: 1.7743x; 1.7743x over previous
#include <cuda_runtime.h>
#include <cuda_fp16.h>

#define BSZ 4
#define NSQ 16384
#define SSAMP 8
#define CPL 64
#define RESOL 128
#define HWSZ (RESOL * RESOL)
#define IND 192
#define NPTS (BSZ * NSQ)   // 65536

// ---------------- scratch (static device globals; no allocation) ----------------
__device__ __align__(16) float  g_planesf[(size_t)BSZ * 3 * HWSZ * CPL]; // fp32 channel-last
__device__ __align__(16) __half g_planesh[(size_t)BSZ * 3 * HWSZ * CPL]; // fp16 channel-last
__device__ __align__(16) float  g_feat[(size_t)NPTS * IND];
__device__ __align__(16) float  g_offwt[(size_t)NPTS * 32];              // 24 off + 8 wt
__device__ __align__(16) float  g_auxw[(size_t)NPTS * IND];              // fp32
__device__ float  g_wtsum[NPTS];
__device__ __align__(16) float  g_tmp[(size_t)NPTS * IND];               // fp32
__device__ __align__(16) __half g_Wvh_hi[IND * IND];
__device__ __align__(16) __half g_Wvh_lo[IND * IND];
__device__ __align__(16) __half g_Wouth_hi[IND * IND];
__device__ __align__(16) __half g_Wouth_lo[IND * IND];

// ---------------- 1) transpose planes to channel-last (fp32 + fp16) ----------------
// grid (HW/32, B, 3), block (32, 8)
__global__ void transpose_planes(const float* __restrict__ pxz,
                                 const float* __restrict__ pxy,
                                 const float* __restrict__ pyz) {
    int p = blockIdx.z;
    int b = blockIdx.y;
    int yx0 = blockIdx.x * 32;
    const float* src = (p == 0 ? pxz : (p == 1 ? pxy : pyz)) + (size_t)b * CPL * HWSZ;
    float* dstf = g_planesf + (size_t)(b * 3 + p) * HWSZ * CPL;
    __half* dsth = g_planesh + (size_t)(b * 3 + p) * HWSZ * CPL;

    __shared__ float tile[CPL][33];
    int tx = threadIdx.x, ty = threadIdx.y;
#pragma unroll
    for (int cb = 0; cb < CPL; cb += 8) {
        int c = cb + ty;
        tile[c][tx] = src[(size_t)c * HWSZ + yx0 + tx];
    }
    __syncthreads();
    int t = ty * 32 + tx;
#pragma unroll
    for (int i = 0; i < 2; i++) {
        int e = i * 256 + t;          // 0..511
        int yxl = e >> 4;             // 0..31
        int c4 = (e & 15) * 4;        // 0..60
        float v0 = tile[c4 + 0][yxl], v1 = tile[c4 + 1][yxl];
        float v2 = tile[c4 + 2][yxl], v3 = tile[c4 + 3][yxl];
        size_t off = (size_t)(yx0 + yxl) * CPL + c4;
        *(float4*)(dstf + off) = make_float4(v0, v1, v2, v3);
        __half2 h0 = __floats2half2_rn(v0, v1);
        __half2 h1 = __floats2half2_rn(v2, v3);
        uint2 u;
        u.x = *(unsigned*)&h0;
        u.y = *(unsigned*)&h1;
        *(uint2*)(dsth + off) = u;
    }
}

// ---------------- 1b) split weights to fp16 hi/lo ----------------
__global__ void convert_w(const float* __restrict__ Wv, const float* __restrict__ Wout) {
    int i = blockIdx.x * 256 + threadIdx.x;
    if (i < IND * IND) {
        float v = Wv[i];
        __half h = __float2half_rn(v);
        g_Wvh_hi[i] = h;
        g_Wvh_lo[i] = __float2half_rn(v - __half2float(h));
        float w = Wout[i];
        __half hw = __float2half_rn(w);
        g_Wouth_hi[i] = hw;
        g_Wouth_lo[i] = __float2half_rn(w - __half2float(hw));
    }
}

// ---------------- bilinear corner weights ----------------
__device__ __forceinline__ void bilerp_setup(float u, float v, int& i00, int& i01,
                                             int& i10, int& i11, float& w00, float& w01,
                                             float& w10, float& w11) {
    float x = __saturatef(u) * 127.0f;
    float y = __saturatef(v) * 127.0f;
    float xf = floorf(x), yf = floorf(y);
    int ix0 = (int)xf, iy0 = (int)yf;
    int ix1 = min(ix0 + 1, 127), iy1 = min(iy0 + 1, 127);
    float wx = x - xf, wy = y - yf;
    w00 = (1.0f - wx) * (1.0f - wy);
    w01 = wx * (1.0f - wy);
    w10 = (1.0f - wx) * wy;
    w11 = wx * wy;
    i00 = iy0 * RESOL + ix0; i01 = iy0 * RESOL + ix1;
    i10 = iy1 * RESOL + ix0; i11 = iy1 * RESOL + ix1;
}

// ---------------- 2) sample features at query points (fp32 planes) ----------------
// 24 lanes/pt, 8 ch/lane
__global__ __launch_bounds__(256) void sample_query(const float* __restrict__ qp) {
    int gid = blockIdx.x * 256 + threadIdx.x;
    int pt = gid / 24, lane = gid - pt * 24;
    int c8 = lane * 8;
    int p = c8 >> 6, ch = c8 & 63;
    int b = pt >> 14;
    float px = qp[pt * 3 + 0], py = qp[pt * 3 + 1], pz = qp[pt * 3 + 2];
    float u = (p == 2) ? py : px;
    float v = (p == 1) ? py : pz;
    int i00, i01, i10, i11;
    float w00, w01, w10, w11;
    bilerp_setup(u, v, i00, i01, i10, i11, w00, w01, w10, w11);
    const float* base = g_planesf + (size_t)(b * 3 + p) * HWSZ * CPL + ch;
    float acc[8];
#pragma unroll
    for (int h = 0; h < 2; h++) {
        float4 f00 = *(const float4*)(base + (size_t)i00 * CPL + 4 * h);
        float4 f01 = *(const float4*)(base + (size_t)i01 * CPL + 4 * h);
        float4 f10 = *(const float4*)(base + (size_t)i10 * CPL + 4 * h);
        float4 f11 = *(const float4*)(base + (size_t)i11 * CPL + 4 * h);
        acc[4 * h + 0] = w00 * f00.x + w01 * f01.x + w10 * f10.x + w11 * f11.x;
        acc[4 * h + 1] = w00 * f00.y + w01 * f01.y + w10 * f10.y + w11 * f11.y;
        acc[4 * h + 2] = w00 * f00.z + w01 * f01.z + w10 * f10.z + w11 * f11.z;
        acc[4 * h + 3] = w00 * f00.w + w01 * f01.w + w10 * f10.w + w11 * f11.w;
    }
    float4* o = (float4*)(g_feat + (size_t)pt * IND + c8);
    o[0] = make_float4(acc[0], acc[1], acc[2], acc[3]);
    o[1] = make_float4(acc[4], acc[5], acc[6], acc[7]);
}

// ---------------- 3) fused off+wt predictor: offwt[pt][32] (fp32) ----------------
// block 128 (4 warps), 4 points per warp, grid NPTS/16
__global__ __launch_bounds__(128) void predict_offwt(
    const float* __restrict__ Woff, const float* __restrict__ boff,
    const float* __restrict__ Wwt, const float* __restrict__ bwt) {
    __shared__ float4 Wc4[32 * 48];      // swizzled: [n*48 + (q ^ (n&7))]
    __shared__ float4 featst[4][4][48];
    int tid = threadIdx.x;
    for (int idx = tid; idx < 32 * 48; idx += 128) {
        int n = idx / 48, q = idx - n * 48;
        const float* src = (n < 24) ? (Woff + n * IND + q * 4)
                                    : (Wwt + (n - 24) * IND + q * 4);
        Wc4[n * 48 + (q ^ (n & 7))] = *(const float4*)src;
    }
    int w = tid >> 5, lane = tid & 31;
    int ptbase = blockIdx.x * 16 + w * 4;
    const float4* feat4 = (const float4*)g_feat;
#pragma unroll
    for (int i = 0; i < 6; i++) {
        int idx = lane + i * 32;          // 0..191
        int pl = idx / 48, q = idx - pl * 48;
        featst[w][pl][q] = feat4[(size_t)(ptbase + pl) * 48 + q];
    }
    __syncthreads();
    float acc[4] = {0.f, 0.f, 0.f, 0.f};
    const float4* wrow = &Wc4[lane * 48];
    int swz = lane & 7;
#pragma unroll 4
    for (int q = 0; q < 48; q++) {
        float4 wv = wrow[q ^ swz];
#pragma unroll
        for (int pl = 0; pl < 4; pl++) {
            float4 f = featst[w][pl][q];
            acc[pl] += wv.x * f.x + wv.y * f.y + wv.z * f.z + wv.w * f.w;
        }
    }
    float bsv = (lane < 24) ? __ldg(boff + lane) : __ldg(bwt + lane - 24);
#pragma unroll
    for (int pl = 0; pl < 4; pl++)
        g_offwt[(size_t)(ptbase + pl) * 32 + lane] = acc[pl] + bsv;
}

// ---------------- 4) sample offset points, weighted-accumulate (fp16 planes) -----
__global__ __launch_bounds__(256) void sample_aux(const float* __restrict__ qp) {
    int gid = blockIdx.x * 256 + threadIdx.x;
    int pt = gid / 24, lane = gid - pt * 24;
    int c8 = lane * 8;
    int p = c8 >> 6, ch = c8 & 63;
    int b = pt >> 14;
    float px = qp[pt * 3 + 0], py = qp[pt * 3 + 1], pz = qp[pt * 3 + 2];
    const float* ow = g_offwt + (size_t)pt * 32;
    const __half* base = g_planesh + (size_t)(b * 3 + p) * HWSZ * CPL + ch;
    float acc[8] = {};
    float wts = 0.0f;
#pragma unroll
    for (int s = 0; s < SSAMP; s++) {
        float qx = px + ow[s * 3 + 0];
        float qy = py + ow[s * 3 + 1];
        float qz = pz + ow[s * 3 + 2];
        float wgt = ow[24 + s];
        float u = (p == 2) ? qy : qx;
        float v = (p == 1) ? qy : qz;
        int i00, i01, i10, i11;
        float w00, w01, w10, w11;
        bilerp_setup(u, v, i00, i01, i10, i11, w00, w01, w10, w11);
        w00 *= wgt; w01 *= wgt; w10 *= wgt; w11 *= wgt;
        uint4 q00 = *(const uint4*)(base + (size_t)i00 * CPL);
        uint4 q01 = *(const uint4*)(base + (size_t)i01 * CPL);
        uint4 q10 = *(const uint4*)(base + (size_t)i10 * CPL);
        uint4 q11 = *(const uint4*)(base + (size_t)i11 * CPL);
        const __half2* h00 = (const __half2*)&q00;
        const __half2* h01 = (const __half2*)&q01;
        const __half2* h10 = (const __half2*)&q10;
        const __half2* h11 = (const __half2*)&q11;
#pragma unroll
        for (int i = 0; i < 4; i++) {
            float2 f00 = __half22float2(h00[i]);
            float2 f01 = __half22float2(h01[i]);
            float2 f10 = __half22float2(h10[i]);
            float2 f11 = __half22float2(h11[i]);
            acc[2 * i + 0] += w00 * f00.x + w01 * f01.x + w10 * f10.x + w11 * f11.x;
            acc[2 * i + 1] += w00 * f00.y + w01 * f01.y + w10 * f10.y + w11 * f11.y;
        }
        wts += wgt;
    }
    float4* o = (float4*)(g_auxw + (size_t)pt * IND + c8);
    o[0] = make_float4(acc[0], acc[1], acc[2], acc[3]);
    o[1] = make_float4(acc[4], acc[5], acc[6], acc[7]);
    if (lane == 0) g_wtsum[pt] = wts;
}

// ---------------- 5) split-fp16 tensor-core GEMM (fp32-accurate) ----------------
// C = A @ W^T + epilogue,  A fp32 (split on the fly), W pre-split hi/lo fp16.
// mode 0: A=g_auxw, W=Wv,  C = acc + bias[n]*wtsum[m]        -> g_tmp (fp32)
// mode 1: A=g_tmp,  W=Wout, C = acc + bias[n] + feat[m][n]   -> outF (fp32)
// grid (NPTS/128, 3), block 256 (8 warps: 4m x 2n, warp tile 32x32)
__device__ __forceinline__ void mma16816(float* c, const unsigned* a, const unsigned* b) {
    asm volatile(
        "mma.sync.aligned.m16n8k16.row.col.f32.f16.f16.f32 "
        "{%0,%1,%2,%3}, {%4,%5,%6,%7}, {%8,%9}, {%0,%1,%2,%3};\n"
        : "+f"(c[0]), "+f"(c[1]), "+f"(c[2]), "+f"(c[3])
        : "r"(a[0]), "r"(a[1]), "r"(a[2]), "r"(a[3]), "r"(b[0]), "r"(b[1]));
}
__device__ __forceinline__ void split2(float2 v, unsigned& hi, unsigned& lo) {
    __half2 h = __floats2half2_rn(v.x, v.y);
    float2 hf = __half22float2(h);
    __half2 l = __floats2half2_rn(v.x - hf.x, v.y - hf.y);
    hi = *(unsigned*)&h;
    lo = *(unsigned*)&l;
}

__global__ __launch_bounds__(256) void gemm_split(int mode,
                                                  const float* __restrict__ bias,
                                                  float* __restrict__ outF) {
    const float* A = (mode == 0) ? g_auxw : g_tmp;
    const __half* Bh = (mode == 0) ? g_Wvh_hi : g_Wouth_hi;
    const __half* Bl = (mode == 0) ? g_Wvh_lo : g_Wouth_lo;
    int tid = threadIdx.x, wid = tid >> 5, lane = tid & 31;
    int g = lane >> 2, t = lane & 3;
    int m_base = blockIdx.x * 128 + (wid >> 1) * 32;
    int n_base = blockIdx.y * 64 + (wid & 1) * 32;

    float c[2][4][4];
#pragma unroll
    for (int i = 0; i < 2; i++)
#pragma unroll
        for (int j = 0; j < 4; j++)
#pragma unroll
            for (int k = 0; k < 4; k++) c[i][j][k] = 0.0f;

    const float* Ap = A + (size_t)(m_base + g) * IND + 2 * t;
    const __half* Bph = Bh + (size_t)(n_base + g) * IND + 2 * t;
    const __half* Bpl = Bl + (size_t)(n_base + g) * IND + 2 * t;

#pragma unroll 2
    for (int kt = 0; kt < 12; kt++) {
        int k0 = kt * 16;
        unsigned ah[2][4], al[2][4], bh[4][2], bl[4][2];
#pragma unroll
        for (int ms = 0; ms < 2; ms++) {
            const float* p = Ap + (size_t)ms * 16 * IND + k0;
            split2(*(const float2*)(p), ah[ms][0], al[ms][0]);
            split2(*(const float2*)(p + 8 * IND), ah[ms][1], al[ms][1]);
            split2(*(const float2*)(p + 8), ah[ms][2], al[ms][2]);
            split2(*(const float2*)(p + 8 * IND + 8), ah[ms][3], al[ms][3]);
        }
#pragma unroll
        for (int ns = 0; ns < 4; ns++) {
            const __half* ph = Bph + (size_t)ns * 8 * IND + k0;
            const __half* pl = Bpl + (size_t)ns * 8 * IND + k0;
            bh[ns][0] = *(const unsigned*)ph;
            bh[ns][1] = *(const unsigned*)(ph + 8);
            bl[ns][0] = *(const unsigned*)pl;
            bl[ns][1] = *(const unsigned*)(pl + 8);
        }
#pragma unroll
        for (int ms = 0; ms < 2; ms++)
#pragma unroll
            for (int ns = 0; ns < 4; ns++) {
                mma16816(c[ms][ns], ah[ms], bh[ns]);
                mma16816(c[ms][ns], ah[ms], bl[ns]);
                mma16816(c[ms][ns], al[ms], bh[ns]);
            }
    }

#pragma unroll
    for (int ms = 0; ms < 2; ms++) {
        int r0 = m_base + ms * 16 + g;
        int r1 = r0 + 8;
        float rs0 = 1.0f, rs1 = 1.0f;
        if (mode == 0) { rs0 = g_wtsum[r0]; rs1 = g_wtsum[r1]; }
#pragma unroll
        for (int ns = 0; ns < 4; ns++) {
            int nc = n_base + ns * 8 + 2 * t;
            float b0 = bias[nc], b1 = bias[nc + 1];
            float v00 = c[ms][ns][0] + b0 * rs0;
            float v01 = c[ms][ns][1] + b1 * rs0;
            float v10 = c[ms][ns][2] + b0 * rs1;
            float v11 = c[ms][ns][3] + b1 * rs1;
            if (mode == 0) {
                *(float2*)(g_tmp + (size_t)r0 * IND + nc) = make_float2(v00, v01);
                *(float2*)(g_tmp + (size_t)r1 * IND + nc) = make_float2(v10, v11);
            } else {
                float2 f0 = *(const float2*)(g_feat + (size_t)r0 * IND + nc);
                float2 f1 = *(const float2*)(g_feat + (size_t)r1 * IND + nc);
                *(float2*)(outF + (size_t)r0 * IND + nc) = make_float2(v00 + f0.x, v01 + f0.y);
                *(float2*)(outF + (size_t)r1 * IND + nc) = make_float2(v10 + f1.x, v11 + f1.y);
            }
        }
    }
}

// ---------------- launch ----------------
extern "C" void kernel_launch(void* const* d_in, const int* in_sizes, int n_in,
                              void* d_out, int out_size) {
    const float* qp    = (const float*)d_in[0];
    const float* fxz   = (const float*)d_in[1];
    const float* fxy   = (const float*)d_in[2];
    const float* fyz   = (const float*)d_in[3];
    const float* W_v   = (const float*)d_in[4];
    const float* b_v   = (const float*)d_in[5];
    const float* W_out = (const float*)d_in[6];
    const float* b_out = (const float*)d_in[7];
    const float* W_off = (const float*)d_in[8];
    const float* b_off = (const float*)d_in[9];
    const float* W_wt  = (const float*)d_in[10];
    const float* b_wt  = (const float*)d_in[11];
    float* out = (float*)d_out;

    // 1) planes -> channel-last fp32+fp16 ; weights -> fp16 hi/lo
    transpose_planes<<<dim3(HWSZ / 32, BSZ, 3), dim3(32, 8)>>>(fxz, fxy, fyz);
    convert_w<<<(IND * IND + 255) / 256, 256>>>(W_v, W_out);
    // 2) feature at query points (fp32 planes — exact position path)
    sample_query<<<NPTS * 24 / 256, 256>>>(qp);
    // 3) off/wt prediction (fp32)
    predict_offwt<<<NPTS / 16, 128>>>(W_off, b_off, W_wt, b_wt);
    // 4) weighted aux accumulation (fp16 planes, fp32 out)
    sample_aux<<<NPTS * 24 / 256, 256>>>(qp);
    // 5) tmp = auxw @ W_v^T + b_v*wtsum   (split-fp16 HMMA, fp32-accurate)
    gemm_split<<<dim3(NPTS / 128, 3), 256>>>(0, b_v, nullptr);
    // 6) out = tmp @ W_out^T + b_out + feat
    gemm_split<<<dim3(NPTS / 128, 3), 256>>>(1, b_out, out);
}